// round 1
// baseline (speedup 1.0000x reference)
#include <cuda_runtime.h>
#include <cstdint>

// ParallelLinear: out[b,t,o] = sum_i x[b,t,i] * W[t,o,i] + bias[t,o]
// B=512, T=1024, ISIZE=OSIZE=64, fp32.
// Strategy: per-block (t, 256 rows). W[t] transposed+swizzled in smem,
// x staged coalesced in smem, packed f32x2 FMA (2 outputs per instr),
// results staged back through smem for coalesced stores.

#define TT   1024
#define BB   512
#define KK   64
#define OO   64
#define BLOCK 128
#define ROWS  256          // rows per block (2 per thread)
#define XSTR  66           // padded smem row stride (floats): conflict-free + 8B-aligned pairs

typedef unsigned long long u64;

__device__ __forceinline__ u64 pack2(float a, float b) {
    u64 r;
    asm("mov.b64 %0, {%1, %2};" : "=l"(r) : "f"(a), "f"(b));
    return r;
}

__device__ __forceinline__ void fma2(u64 &d, u64 a, u64 b) {
    asm("fma.rn.f32x2 %0, %1, %2, %3;" : "=l"(d) : "l"(a), "l"(b), "l"(d));
}

__global__ __launch_bounds__(BLOCK, 2)
void ParallelLinear_59133109732019_kernel(
    const float* __restrict__ x,     // [B, T, 64]
    const float* __restrict__ W,     // [T, 64, 64]  (W[t][o][i])
    const float* __restrict__ bias,  // [T, 64]
    float* __restrict__ out)         // [B, T, 64]
{
    extern __shared__ float smem[];
    float* sW = smem;                 // 4096 floats: sW[i*64 + (o ^ ((i&7)<<2))] = W[t][o][i]
    float* sB = smem + 4096;          // 64 floats
    float* xs = smem + 4096 + 64;     // 256 * 66 floats (x tile, later out tile)

    const int t       = blockIdx.y;
    const int rowBase = blockIdx.x * ROWS;
    const int tid     = threadIdx.x;

    // ---- stage W[t] transposed with float4-granular XOR swizzle ----
    const float* Wt = W + (size_t)t * (OO * KK);
    #pragma unroll
    for (int k = 0; k < (OO * KK) / BLOCK; k++) {
        int idx = k * BLOCK + tid;          // coalesced global read
        int o = idx >> 6, i = idx & 63;
        sW[i * 64 + (o ^ ((i & 7) << 2))] = Wt[idx];
    }
    if (tid < OO) sB[tid] = bias[(size_t)t * OO + tid];

    // ---- stage x tile (coalesced: 128B per warp-load) ----
    #pragma unroll
    for (int k = 0; k < (ROWS * KK) / BLOCK; k++) {
        int f   = k * BLOCK + tid;
        int row = f >> 6, i = f & 63;
        xs[row * XSTR + i] =
            x[(size_t)(rowBase + row) * (TT * KK) + (size_t)t * KK + i];
    }
    __syncthreads();

    // ---- compute: thread handles rows tid and tid+128, all 64 outputs each ----
    u64 acc0[32], acc1[32];
    #pragma unroll
    for (int p = 0; p < 32; p++) {
        u64 bb = *(const u64*)(sB + 2 * p);
        acc0[p] = bb;
        acc1[p] = bb;
    }

    const float* xr0 = xs + tid * XSTR;
    const float* xr1 = xs + (tid + BLOCK) * XSTR;

    #pragma unroll 2
    for (int i = 0; i < KK; i++) {
        float xv0 = xr0[i];                 // conflict-free (stride 66 -> 2-way worst)
        float xv1 = xr1[i];
        u64 xx0 = pack2(xv0, xv0);
        u64 xx1 = pack2(xv1, xv1);
        const float* wrow = sW + i * 64;
        int sw = i & 7;
        #pragma unroll
        for (int m = 0; m < 16; m++) {
            // broadcast LDS.128: two o-pairs (o=4m..4m+3) after de-swizzle
            const longlong2 wv = *(const longlong2*)(wrow + 4 * (m ^ sw));
            u64 wx = (u64)wv.x;             // (W[4m][i],   W[4m+1][i])
            u64 wy = (u64)wv.y;             // (W[4m+2][i], W[4m+3][i])
            fma2(acc0[2 * m],     xx0, wx);
            fma2(acc0[2 * m + 1], xx0, wy);
            fma2(acc1[2 * m],     xx1, wx);
            fma2(acc1[2 * m + 1], xx1, wy);
        }
    }

    // ---- stage results into xs (each thread owns its rows; no race) ----
    float* or0 = xs + tid * XSTR;
    float* or1 = xs + (tid + BLOCK) * XSTR;
    #pragma unroll
    for (int p = 0; p < 32; p++) {
        *(u64*)(or0 + 2 * p) = acc0[p];
        *(u64*)(or1 + 2 * p) = acc1[p];
    }
    __syncthreads();

    // ---- coalesced global store: one warp writes one full 256B row per instr ----
    #pragma unroll
    for (int k = 0; k < (ROWS * OO / 2) / BLOCK; k++) {
        int f   = k * BLOCK + tid;
        int row = f >> 5, p = f & 31;
        u64 v = *(const u64*)(xs + row * XSTR + 2 * p);
        *(u64*)(out + (size_t)(rowBase + row) * (TT * OO) + (size_t)t * OO + 2 * p) = v;
    }
}

extern "C" void kernel_launch(void* const* d_in, const int* in_sizes, int n_in,
                              void* d_out, int out_size)
{
    const float* x    = (const float*)d_in[0];   // 512*1024*8*8 fp32
    const float* W    = (const float*)d_in[1];   // 1024*64*64 fp32
    const float* bias = (const float*)d_in[2];   // 1024*64 fp32
    float* out        = (float*)d_out;           // 512*1024*64 fp32

    const int smem_bytes = (4096 + 64 + ROWS * XSTR) * (int)sizeof(float); // 84224
    cudaFuncSetAttribute(ParallelLinear_59133109732019_kernel,
                         cudaFuncAttributeMaxDynamicSharedMemorySize, smem_bytes);

    dim3 grid(BB / ROWS, TT);   // (2, 1024)
    ParallelLinear_59133109732019_kernel<<<grid, BLOCK, smem_bytes>>>(x, W, bias, out);
}

// round 2
// speedup vs baseline: 1.4025x; 1.4025x over previous
#include <cuda_runtime.h>
#include <cstdint>

// ParallelLinear: out[b,t,o] = sum_i x[b,t,i] * W[t,o,i] + bias[t,o]
// B=512, T=1024, ISIZE=OSIZE=64, fp32.
// R2: 2 rows x 32 outputs per thread (64 u64 accs -> no spill),
// stride-68 padded W (no swizzle ALU on read path), f32x2 packed FMA.

#define TT    1024
#define BB    512
#define KK    64
#define OO    64
#define BLOCK 128
#define ROWS  128          // rows per block (2 per thread, split-o across pairs)
#define WSTR  68           // W smem stride (floats): 16B-aligned, 4-way write conflict only
#define XSTR  66           // x/out smem stride (floats): 2-way worst, 8B-aligned

typedef unsigned long long u64;

__device__ __forceinline__ u64 pack2(float a, float b) {
    u64 r;
    asm("mov.b64 %0, {%1, %2};" : "=l"(r) : "f"(a), "f"(b));
    return r;
}

__device__ __forceinline__ void fma2(u64 &d, u64 a, u64 b) {
    asm("fma.rn.f32x2 %0, %1, %2, %3;" : "=l"(d) : "l"(a), "l"(b), "l"(d));
}

__global__ __launch_bounds__(BLOCK, 4)
void ParallelLinear_59133109732019_kernel(
    const float* __restrict__ x,     // [B, T, 64]
    const float* __restrict__ W,     // [T, 64, 64]  (W[t][o][i])
    const float* __restrict__ bias,  // [T, 64]
    float* __restrict__ out)         // [B, T, 64]
{
    extern __shared__ float smem[];
    float* sW = smem;                     // 64*WSTR: sW[i*WSTR + o] = W[t][o][i]
    float* sB = smem + KK * WSTR;         // 64
    float* xs = sB + OO;                  // 128*XSTR (x tile, later out tile)

    const int t       = blockIdx.y;
    const int rowBase = blockIdx.x * ROWS;
    const int tid     = threadIdx.x;
    const int half    = tid >> 6;         // output half: o in [32*half, 32*half+32)
    const int r       = tid & 63;         // rows r and r+64

    // ---- stage W[t] transposed into padded smem (coalesced gmem reads) ----
    const float* Wt = W + (size_t)t * (OO * KK);
    #pragma unroll
    for (int k = 0; k < (OO * KK) / BLOCK; k++) {
        int idx = k * BLOCK + tid;
        int o = idx >> 6, i = idx & 63;
        sW[i * WSTR + o] = Wt[idx];
    }
    if (tid < OO) sB[tid] = bias[(size_t)t * OO + tid];

    // ---- stage x tile (coalesced) ----
    #pragma unroll
    for (int k = 0; k < (ROWS * KK) / BLOCK; k++) {
        int f   = k * BLOCK + tid;
        int row = f >> 6, i = f & 63;
        xs[row * XSTR + i] =
            x[(size_t)(rowBase + row) * (TT * KK) + (size_t)t * KK + i];
    }
    __syncthreads();

    // ---- accumulators: 2 rows x 32 outputs = 32 f32x2 pairs ----
    const int obase = half << 5;
    u64 acc0[16], acc1[16];
    #pragma unroll
    for (int p = 0; p < 16; p++) {
        u64 bb = *(const u64*)(sB + obase + 2 * p);
        acc0[p] = bb;
        acc1[p] = bb;
    }

    const float* xr0 = xs + r * XSTR;
    const float* xr1 = xs + (r + 64) * XSTR;
    const float* wp  = sW + obase;

    #pragma unroll 8
    for (int i = 0; i < KK; i++) {
        float xv0 = xr0[i];
        float xv1 = xr1[i];
        u64 xx0 = pack2(xv0, xv0);
        u64 xx1 = pack2(xv1, xv1);
        const float* wrow = wp + i * WSTR;   // uniform per warp -> broadcast LDS.128
        #pragma unroll
        for (int mm = 0; mm < 8; mm++) {
            const longlong2 wv = *(const longlong2*)(wrow + 4 * mm);
            u64 wx = (u64)wv.x;              // (W[o][i],   W[o+1][i])
            u64 wy = (u64)wv.y;              // (W[o+2][i], W[o+3][i])
            fma2(acc0[2 * mm],     xx0, wx);
            fma2(acc0[2 * mm + 1], xx0, wy);
            fma2(acc1[2 * mm],     xx1, wx);
            fma2(acc1[2 * mm + 1], xx1, wy);
        }
    }

    __syncthreads();   // everyone done reading xs before it becomes the out tile

    // ---- stage results (each thread owns rows r, r+64 in its o-half) ----
    float* or0 = xs + r * XSTR + obase;
    float* or1 = xs + (r + 64) * XSTR + obase;
    #pragma unroll
    for (int p = 0; p < 16; p++) {
        *(u64*)(or0 + 2 * p) = acc0[p];
        *(u64*)(or1 + 2 * p) = acc1[p];
    }
    __syncthreads();

    // ---- coalesced global stores (256B per warp-instr group) ----
    #pragma unroll
    for (int k = 0; k < (ROWS * OO / 2) / BLOCK; k++) {
        int f   = k * BLOCK + tid;
        int row = f >> 5, p = f & 31;
        u64 v = *(const u64*)(xs + row * XSTR + 2 * p);
        *(u64*)(out + (size_t)(rowBase + row) * (TT * OO) + (size_t)t * OO + 2 * p) = v;
    }
}

extern "C" void kernel_launch(void* const* d_in, const int* in_sizes, int n_in,
                              void* d_out, int out_size)
{
    const float* x    = (const float*)d_in[0];   // 512*1024*64 fp32
    const float* W    = (const float*)d_in[1];   // 1024*64*64 fp32
    const float* bias = (const float*)d_in[2];   // 1024*64 fp32
    float* out        = (float*)d_out;           // 512*1024*64 fp32

    const int smem_bytes = (KK * WSTR + OO + ROWS * XSTR) * (int)sizeof(float); // 51456
    cudaFuncSetAttribute(ParallelLinear_59133109732019_kernel,
                         cudaFuncAttributeMaxDynamicSharedMemorySize, smem_bytes);

    dim3 grid(BB / ROWS, TT);   // (4, 1024)
    ParallelLinear_59133109732019_kernel<<<grid, BLOCK, smem_bytes>>>(x, W, bias, out);
}

// round 3
// speedup vs baseline: 1.4801x; 1.0553x over previous
#include <cuda_runtime.h>
#include <cstdint>

// ParallelLinear: out[b,t,o] = sum_i x[b,t,i] * W[t,o,i] + bias[t,o]
// B=512, T=1024, ISIZE=OSIZE=64, fp32.
// R3: 4 rows x 16 outputs per thread; x LDS.128-vectorized over i (stride-68,
// conflict-free); W broadcast LDS.128 reused across 4 rows; f32x2 packed FMA.

#define TT    1024
#define BB    512
#define KK    64
#define OO    64
#define BLOCK 128
#define ROWS  128
#define WSTR  68           // W smem stride (floats), 16B-aligned
#define XSTR  68           // x/out smem stride (floats), 16B-aligned, conflict-free f4

typedef unsigned long long u64;

__device__ __forceinline__ u64 pack2(float a) {
    u64 r;
    asm("mov.b64 %0, {%1, %1};" : "=l"(r) : "f"(a));
    return r;
}

__device__ __forceinline__ void fma2(u64 &d, u64 a, u64 b) {
    asm("fma.rn.f32x2 %0, %1, %2, %3;" : "=l"(d) : "l"(a), "l"(b), "l"(d));
}

__global__ __launch_bounds__(BLOCK, 4)
void ParallelLinear_59133109732019_kernel(
    const float* __restrict__ x,     // [B, T, 64]
    const float* __restrict__ W,     // [T, 64, 64]  (W[t][o][i])
    const float* __restrict__ bias,  // [T, 64]
    float* __restrict__ out)         // [B, T, 64]
{
    extern __shared__ float smem[];
    float* sW = smem;                     // 64*WSTR: sW[i*WSTR + o] = W[t][o][i]
    float* sB = smem + KK * WSTR;         // 64
    float* xs = sB + OO;                  // 128*XSTR (x tile, later out tile)

    const int t       = blockIdx.y;
    const int rowBase = blockIdx.x * ROWS;
    const int tid     = threadIdx.x;
    const int lane    = tid & 31;
    const int obase   = (tid >> 5) << 4;  // warp-uniform: warp w -> outs [16w,16w+16)

    // ---- stage W[t] transposed into padded smem (coalesced gmem reads) ----
    const float* Wt = W + (size_t)t * (OO * KK);
    #pragma unroll
    for (int k = 0; k < (OO * KK) / BLOCK; k++) {
        int idx = k * BLOCK + tid;
        int o = idx >> 6, i = idx & 63;
        sW[i * WSTR + o] = Wt[idx];
    }
    if (tid < OO) sB[tid] = bias[(size_t)t * OO + tid];

    // ---- stage x tile: coalesced float4 global loads ----
    const float4* xg = (const float4*)(x + (size_t)rowBase * (TT * KK) + (size_t)t * KK);
    #pragma unroll
    for (int k = 0; k < (ROWS * KK / 4) / BLOCK; k++) {
        int f   = k * BLOCK + tid;
        int row = f >> 4, j = f & 15;                 // 16 float4 per row
        float4 v = xg[(size_t)row * (TT * KK / 4) + j];
        *(float4*)(xs + row * XSTR + 4 * j) = v;
    }
    __syncthreads();

    // ---- accumulators: 4 rows x 16 outputs = 32 f32x2 pairs ----
    u64 acc[4][8];
    #pragma unroll
    for (int p = 0; p < 8; p++) {
        u64 bb = *(const u64*)(sB + obase + 2 * p);
        acc[0][p] = bb; acc[1][p] = bb; acc[2][p] = bb; acc[3][p] = bb;
    }

    const float* xr[4];
    #pragma unroll
    for (int r = 0; r < 4; r++) xr[r] = xs + (lane + 32 * r) * XSTR;
    const float* wp = sW + obase;

    #pragma unroll 4
    for (int i0 = 0; i0 < KK; i0 += 4) {
        float4 xv[4];
        #pragma unroll
        for (int r = 0; r < 4; r++)
            xv[r] = *(const float4*)(xr[r] + i0);     // conflict-free LDS.128

        #pragma unroll
        for (int di = 0; di < 4; di++) {
            const float* wrow = wp + (i0 + di) * WSTR;    // warp-uniform -> broadcast
            longlong2 w01 = *(const longlong2*)(wrow);
            longlong2 w23 = *(const longlong2*)(wrow + 4);
            longlong2 w45 = *(const longlong2*)(wrow + 8);
            longlong2 w67 = *(const longlong2*)(wrow + 12);

            u64 xx[4];
            xx[0] = pack2(di == 0 ? xv[0].x : di == 1 ? xv[0].y : di == 2 ? xv[0].z : xv[0].w);
            xx[1] = pack2(di == 0 ? xv[1].x : di == 1 ? xv[1].y : di == 2 ? xv[1].z : xv[1].w);
            xx[2] = pack2(di == 0 ? xv[2].x : di == 1 ? xv[2].y : di == 2 ? xv[2].z : xv[2].w);
            xx[3] = pack2(di == 0 ? xv[3].x : di == 1 ? xv[3].y : di == 2 ? xv[3].z : xv[3].w);

            #pragma unroll
            for (int r = 0; r < 4; r++) {
                fma2(acc[r][0], xx[r], (u64)w01.x);
                fma2(acc[r][1], xx[r], (u64)w01.y);
                fma2(acc[r][2], xx[r], (u64)w23.x);
                fma2(acc[r][3], xx[r], (u64)w23.y);
                fma2(acc[r][4], xx[r], (u64)w45.x);
                fma2(acc[r][5], xx[r], (u64)w45.y);
                fma2(acc[r][6], xx[r], (u64)w67.x);
                fma2(acc[r][7], xx[r], (u64)w67.y);
            }
        }
    }

    __syncthreads();   // all reads of xs done before reuse as out tile

    // ---- stage results: thread owns rows {lane+32r} cols [obase,obase+16) ----
    #pragma unroll
    for (int r = 0; r < 4; r++) {
        float* orow = xs + (lane + 32 * r) * XSTR + obase;
        #pragma unroll
        for (int p = 0; p < 8; p++)
            *(u64*)(orow + 2 * p) = acc[r][p];
    }
    __syncthreads();

    // ---- coalesced float4 global stores ----
    float4* og = (float4*)(out + (size_t)rowBase * (TT * OO) + (size_t)t * OO);
    #pragma unroll
    for (int k = 0; k < (ROWS * OO / 4) / BLOCK; k++) {
        int f   = k * BLOCK + tid;
        int row = f >> 4, j = f & 15;
        float4 v = *(const float4*)(xs + row * XSTR + 4 * j);
        og[(size_t)row * (TT * OO / 4) + j] = v;
    }
}

extern "C" void kernel_launch(void* const* d_in, const int* in_sizes, int n_in,
                              void* d_out, int out_size)
{
    const float* x    = (const float*)d_in[0];   // 512*1024*64 fp32
    const float* W    = (const float*)d_in[1];   // 1024*64*64 fp32
    const float* bias = (const float*)d_in[2];   // 1024*64 fp32
    float* out        = (float*)d_out;           // 512*1024*64 fp32

    const int smem_bytes = (KK * WSTR + OO + ROWS * XSTR) * (int)sizeof(float); // 52480
    cudaFuncSetAttribute(ParallelLinear_59133109732019_kernel,
                         cudaFuncAttributeMaxDynamicSharedMemorySize, smem_bytes);

    dim3 grid(BB / ROWS, TT);   // (4, 1024)
    ParallelLinear_59133109732019_kernel<<<grid, BLOCK, smem_bytes>>>(x, W, bias, out);
}

// round 5
// speedup vs baseline: 2.2215x; 1.5009x over previous
#include <cuda_runtime.h>
#include <cuda_bf16.h>
#include <cstdint>

// ParallelLinear: out[b,t,o] = sum_i x[b,t,i] * W[t,o,i] + bias[t,o]
// B=512, T=1024, ISIZE=OSIZE=64, fp32.
// R5: warp-level mma.sync bf16-split emulated fp32 (tcgen05 unavailable: harness
// targets plain sm_103). D = Ahi*Bhi + Ahi*Blo + Alo*Bhi, fp32 accum.
// Swizzled smem tiles + ldmatrix, direct full-sector STG.64 epilogue.

#define TT    1024
#define BB    512
#define KK    64
#define OO    64
#define BLOCK 128
#define ROWS  128

typedef unsigned int u32;

// ---- smem byte offsets ----
#define SM_BIAS 0                          // 64 floats = 256 B
#define SM_AHI  256                        // 128 rows * 128 B
#define SM_ALO  (SM_AHI + ROWS * 128)      // 16640
#define SM_BHI  (SM_ALO + ROWS * 128)      // 33024 (64 rows * 128 B)
#define SM_BLO  (SM_BHI + OO * 128)        // 41216
#define SM_TOTAL (SM_BLO + OO * 128)       // 49408

__device__ __forceinline__ u32 smem_u32(const void* p) {
    u32 a;
    asm("{ .reg .u64 t; cvta.to.shared.u64 t, %1; cvt.u32.u64 %0, t; }" : "=r"(a) : "l"(p));
    return a;
}

// split fp32 pair -> packed bf16x2 hi and lo
__device__ __forceinline__ void split2(float2 v, u32 &hi, u32 &lo) {
    __nv_bfloat16 h0 = __float2bfloat16(v.x);
    __nv_bfloat16 h1 = __float2bfloat16(v.y);
    __nv_bfloat162 hp(h0, h1);
    __nv_bfloat162 lp(__float2bfloat16(v.x - __bfloat162float(h0)),
                      __float2bfloat16(v.y - __bfloat162float(h1)));
    hi = *(u32*)&hp;
    lo = *(u32*)&lp;
}

// staging-write offset: row-major tile, 128 B/row, 16B chunks XOR-swizzled by row&7
__device__ __forceinline__ u32 stage_off(int row, int ip) {   // ip = bf16-pair index 0..31
    return (u32)(row * 128 + ((((ip >> 2) ^ (row & 7)) & 7) << 4) + ((ip & 3) << 2));
}

__device__ __forceinline__ void ldmx4(u32 &r0, u32 &r1, u32 &r2, u32 &r3, u32 addr) {
    asm volatile("ldmatrix.sync.aligned.m8n8.x4.shared.b16 {%0,%1,%2,%3}, [%4];"
                 : "=r"(r0), "=r"(r1), "=r"(r2), "=r"(r3) : "r"(addr));
}

__device__ __forceinline__ void mma_bf16(float* d, const u32* a, u32 b0, u32 b1) {
    asm volatile(
        "mma.sync.aligned.m16n8k16.row.col.f32.bf16.bf16.f32 "
        "{%0,%1,%2,%3}, {%4,%5,%6,%7}, {%8,%9}, {%0,%1,%2,%3};"
        : "+f"(d[0]), "+f"(d[1]), "+f"(d[2]), "+f"(d[3])
        : "r"(a[0]), "r"(a[1]), "r"(a[2]), "r"(a[3]), "r"(b0), "r"(b1));
}

__global__ __launch_bounds__(BLOCK, 4)
void ParallelLinear_59133109732019_kernel(
    const float* __restrict__ x,     // [B, T, 64]
    const float* __restrict__ W,     // [T, 64, 64]  (W[t][o][i])
    const float* __restrict__ bias,  // [T, 64]
    float* __restrict__ out)         // [B, T, 64]
{
    extern __shared__ char smem[];
    const u32 sb = smem_u32(smem);

    const int t       = blockIdx.y;
    const int rowBase = blockIdx.x * ROWS;
    const int tid     = threadIdx.x;
    const int wid     = tid >> 5;
    const int lane    = tid & 31;

    if (tid < OO) ((float*)(smem + SM_BIAS))[tid] = bias[(size_t)t * OO + tid];

    // ---- stage W[t] hi/lo (coalesced float2 loads; one warp fills one 128B row) ----
    {
        const float2* Wg = (const float2*)(W + (size_t)t * (OO * KK));
        #pragma unroll
        for (int k = 0; k < (OO * KK / 2) / BLOCK; k++) {   // 16 iters
            int p = k * BLOCK + tid;
            int row = p >> 5, ip = p & 31;                  // row = o (n), ip -> i pair
            u32 hi, lo;
            split2(Wg[p], hi, lo);
            u32 off = stage_off(row, ip);
            *(u32*)(smem + SM_BHI + off) = hi;
            *(u32*)(smem + SM_BLO + off) = lo;
        }
    }

    // ---- stage x tile hi/lo ----
    {
        const float2* xg = (const float2*)(x + (size_t)rowBase * (TT * KK) + (size_t)t * KK);
        #pragma unroll
        for (int k = 0; k < (ROWS * KK / 2) / BLOCK; k++) { // 32 iters
            int p = k * BLOCK + tid;
            int row = p >> 5, ip = p & 31;
            u32 hi, lo;
            split2(xg[(size_t)row * (TT * KK / 2) + ip], hi, lo);
            u32 off = stage_off(row, ip);
            *(u32*)(smem + SM_AHI + off) = hi;
            *(u32*)(smem + SM_ALO + off) = lo;
        }
    }
    __syncthreads();

    // ---- accumulators: 2 m-tiles x 8 n-tiles x 4 fp32 ----
    float d[2][8][4];
    #pragma unroll
    for (int mt = 0; mt < 2; mt++)
        #pragma unroll
        for (int nt = 0; nt < 8; nt++)
            #pragma unroll
            for (int e = 0; e < 4; e++) d[mt][nt][e] = 0.0f;

    // ldmatrix lane->address components
    const int a_row  = lane & 15;          // + warp/mt base
    const int a_cadd = lane >> 4;          // chunk add
    const int b_row  = (lane & 7) + ((lane >> 4) << 3);   // n within 16-block
    const int b_cadd = (lane >> 3) & 1;

    #pragma unroll
    for (int ks = 0; ks < 4; ks++) {
        const int c0 = ks * 2;             // 16B-chunk index of k0 = 16*ks

        u32 ah[2][4], al[2][4];
        #pragma unroll
        for (int mt = 0; mt < 2; mt++) {
            int row = wid * 32 + mt * 16 + a_row;
            int ch  = c0 + a_cadd;
            u32 off = (u32)(row * 128 + (((ch ^ (row & 7)) & 7) << 4));
            ldmx4(ah[mt][0], ah[mt][1], ah[mt][2], ah[mt][3], sb + SM_AHI + off);
            ldmx4(al[mt][0], al[mt][1], al[mt][2], al[mt][3], sb + SM_ALO + off);
        }

        #pragma unroll
        for (int np = 0; np < 4; np++) {   // n-tile pair (nt = 2np, 2np+1)
            int n  = np * 16 + b_row;
            int ch = c0 + b_cadd;
            u32 off = (u32)(n * 128 + (((ch ^ (n & 7)) & 7) << 4));
            u32 bh0, bh1, bh2, bh3, bl0, bl1, bl2, bl3;
            ldmx4(bh0, bh1, bh2, bh3, sb + SM_BHI + off);
            ldmx4(bl0, bl1, bl2, bl3, sb + SM_BLO + off);

            #pragma unroll
            for (int mt = 0; mt < 2; mt++) {
                mma_bf16(d[mt][2 * np],     ah[mt], bh0, bh1);   // hi*hi
                mma_bf16(d[mt][2 * np + 1], ah[mt], bh2, bh3);
                mma_bf16(d[mt][2 * np],     ah[mt], bl0, bl1);   // hi*lo
                mma_bf16(d[mt][2 * np + 1], ah[mt], bl2, bl3);
                mma_bf16(d[mt][2 * np],     al[mt], bh0, bh1);   // lo*hi
                mma_bf16(d[mt][2 * np + 1], al[mt], bh2, bh3);
            }
        }
    }

    // ---- epilogue: +bias, direct stores (each STG.64 group = 8 full 32B sectors) ----
    const float* sBias = (const float*)(smem + SM_BIAS);
    #pragma unroll
    for (int mt = 0; mt < 2; mt++) {
        int r0 = rowBase + wid * 32 + mt * 16 + (lane >> 2);
        float* o0 = out + (size_t)r0 * (TT * OO) + (size_t)t * OO;
        float* o1 = o0 + (size_t)8 * (TT * OO);
        #pragma unroll
        for (int nt = 0; nt < 8; nt++) {
            int c = nt * 8 + 2 * (lane & 3);
            float2 bv = *(const float2*)(sBias + c);
            float2 v0 = { d[mt][nt][0] + bv.x, d[mt][nt][1] + bv.y };
            float2 v1 = { d[mt][nt][2] + bv.x, d[mt][nt][3] + bv.y };
            *(float2*)(o0 + c) = v0;   // row r0
            *(float2*)(o1 + c) = v1;   // row r0 + 8
        }
    }
}

extern "C" void kernel_launch(void* const* d_in, const int* in_sizes, int n_in,
                              void* d_out, int out_size)
{
    const float* x    = (const float*)d_in[0];   // 512*1024*64 fp32
    const float* W    = (const float*)d_in[1];   // 1024*64*64 fp32
    const float* bias = (const float*)d_in[2];   // 1024*64 fp32
    float* out        = (float*)d_out;           // 512*1024*64 fp32

    cudaFuncSetAttribute(ParallelLinear_59133109732019_kernel,
                         cudaFuncAttributeMaxDynamicSharedMemorySize, SM_TOTAL);

    dim3 grid(BB / ROWS, TT);   // (4, 1024)
    ParallelLinear_59133109732019_kernel<<<grid, BLOCK, SM_TOTAL>>>(x, W, bias, out);
}

// round 6
// speedup vs baseline: 2.5041x; 1.1273x over previous
#include <cuda_runtime.h>
#include <cuda_bf16.h>
#include <cstdint>

// ParallelLinear: out[b,t,o] = sum_i x[b,t,i] * W[t,o,i] + bias[t,o]
// B=512, T=1024, ISIZE=OSIZE=64, fp32.
// R6: mma.sync bf16-split fp32 (D = Ahi*Bhi + Ahi*Blo + Alo*Bhi).
//   x loaded DIRECTLY from global into A fragments (sector-perfect LDG.64),
//   hi/lo split in registers, software-pipelined one k-step ahead.
//   Only W (hi/lo) + bias staged in smem; ldmatrix for B fragments.

#define TT    1024
#define BB    512
#define KK    64
#define OO    64
#define BLOCK 128
#define ROWS  128

typedef unsigned int u32;

// ---- smem byte offsets ----
#define SM_BIAS 0                          // 64 floats = 256 B
#define SM_BHI  256                        // 64 rows * 128 B = 8192
#define SM_BLO  (SM_BHI + OO * 128)        // 8448
#define SM_TOTAL (SM_BLO + OO * 128)       // 16640

__device__ __forceinline__ u32 smem_u32(const void* p) {
    u32 a;
    asm("{ .reg .u64 t; cvta.to.shared.u64 t, %1; cvt.u32.u64 %0, t; }" : "=r"(a) : "l"(p));
    return a;
}

// split fp32 pair -> packed bf16x2 hi and lo
__device__ __forceinline__ void split2(float2 v, u32 &hi, u32 &lo) {
    __nv_bfloat162 hp = __float22bfloat162_rn(v);         // .x -> low half
    u32 h = *(u32*)&hp;
    float hx = __uint_as_float(h << 16);                  // back to f32 (exact)
    float hy = __uint_as_float(h & 0xFFFF0000u);
    float2 r = { v.x - hx, v.y - hy };
    __nv_bfloat162 lp = __float22bfloat162_rn(r);
    hi = h;
    lo = *(u32*)&lp;
}

// W staging-write offset: row-major tile, 128 B/row, 16B chunks XOR-swizzled by row&7
__device__ __forceinline__ u32 stage_off(int row, int ip) {   // ip = bf16-pair idx 0..31
    return (u32)(row * 128 + ((((ip >> 2) ^ (row & 7)) & 7) << 4) + ((ip & 3) << 2));
}

__device__ __forceinline__ void ldmx4(u32 &r0, u32 &r1, u32 &r2, u32 &r3, u32 addr) {
    asm volatile("ldmatrix.sync.aligned.m8n8.x4.shared.b16 {%0,%1,%2,%3}, [%4];"
                 : "=r"(r0), "=r"(r1), "=r"(r2), "=r"(r3) : "r"(addr));
}

__device__ __forceinline__ void mma_bf16(float* d, const u32* a, u32 b0, u32 b1) {
    asm volatile(
        "mma.sync.aligned.m16n8k16.row.col.f32.bf16.bf16.f32 "
        "{%0,%1,%2,%3}, {%4,%5,%6,%7}, {%8,%9}, {%0,%1,%2,%3};"
        : "+f"(d[0]), "+f"(d[1]), "+f"(d[2]), "+f"(d[3])
        : "r"(a[0]), "r"(a[1]), "r"(a[2]), "r"(a[3]), "r"(b0), "r"(b1));
}

__global__ __launch_bounds__(BLOCK, 4)
void ParallelLinear_59133109732019_kernel(
    const float* __restrict__ x,     // [B, T, 64]
    const float* __restrict__ W,     // [T, 64, 64]  (W[t][o][i])
    const float* __restrict__ bias,  // [T, 64]
    float* __restrict__ out)         // [B, T, 64]
{
    extern __shared__ char smem[];
    const u32 sb = smem_u32(smem);

    const int t       = blockIdx.y;
    const int rowBase = blockIdx.x * ROWS;
    const int tid     = threadIdx.x;
    const int wid     = tid >> 5;
    const int lane    = tid & 31;
    const int g       = lane >> 2;       // row within 8-group
    const int q       = lane & 3;        // col-pair selector

    // x fragment source base: rows (rowBase + wid*32 + mt*16 + g [+8]), col 2q
    const size_t xrstride = (size_t)TT * KK;               // floats per batch-row
    const float* xbase[2];
    #pragma unroll
    for (int mt = 0; mt < 2; mt++)
        xbase[mt] = x + (size_t)(rowBase + wid * 32 + mt * 16 + g) * xrstride
                      + (size_t)t * KK + 2 * q;

    // ---- prefetch ks=0 x data (issues LDGs before W staging; overlaps) ----
    float2 xf[2][4];
    #pragma unroll
    for (int mt = 0; mt < 2; mt++) {
        const float* bp = xbase[mt];
        xf[mt][0] = *(const float2*)(bp);                  // row,   k-low
        xf[mt][1] = *(const float2*)(bp + 8 * xrstride);   // row+8, k-low
        xf[mt][2] = *(const float2*)(bp + 8);              // row,   k-high
        xf[mt][3] = *(const float2*)(bp + 8 * xrstride + 8);
    }

    // ---- stage W[t] hi/lo (coalesced float2 loads) ----
    {
        const float2* Wg = (const float2*)(W + (size_t)t * (OO * KK));
        #pragma unroll
        for (int k = 0; k < (OO * KK / 2) / BLOCK; k++) {  // 16 iters
            int p = k * BLOCK + tid;
            int row = p >> 5, ip = p & 31;                 // row = o (n), ip -> i pair
            u32 hi, lo;
            split2(Wg[p], hi, lo);
            u32 off = stage_off(row, ip);
            *(u32*)(smem + SM_BHI + off) = hi;
            *(u32*)(smem + SM_BLO + off) = lo;
        }
        if (tid < OO) ((float*)(smem + SM_BIAS))[tid] = bias[(size_t)t * OO + tid];
    }
    __syncthreads();

    // ---- accumulators: 2 m-tiles x 8 n-tiles x 4 fp32 ----
    float d[2][8][4];
    #pragma unroll
    for (int mt = 0; mt < 2; mt++)
        #pragma unroll
        for (int nt = 0; nt < 8; nt++)
            #pragma unroll
            for (int e = 0; e < 4; e++) d[mt][nt][e] = 0.0f;

    // B-fragment ldmatrix lane->address components
    const int b_row  = (lane & 7) + ((lane >> 4) << 3);    // n within 16-block
    const int b_cadd = (lane >> 3) & 1;

    #pragma unroll
    for (int ks = 0; ks < 4; ks++) {
        // prefetch next k-step's x while this one computes
        float2 xn[2][4];
        if (ks < 3) {
            #pragma unroll
            for (int mt = 0; mt < 2; mt++) {
                const float* bp = xbase[mt] + (ks + 1) * 16;
                xn[mt][0] = *(const float2*)(bp);
                xn[mt][1] = *(const float2*)(bp + 8 * xrstride);
                xn[mt][2] = *(const float2*)(bp + 8);
                xn[mt][3] = *(const float2*)(bp + 8 * xrstride + 8);
            }
        }

        // convert current f32 fragments -> bf16 hi/lo A fragments
        u32 ah[2][4], al[2][4];
        #pragma unroll
        for (int mt = 0; mt < 2; mt++)
            #pragma unroll
            for (int r = 0; r < 4; r++)
                split2(xf[mt][r], ah[mt][r], al[mt][r]);

        const int c0 = ks * 2;             // 16B-chunk index of k0 = 16*ks
        #pragma unroll
        for (int np = 0; np < 4; np++) {   // n-tile pair (nt = 2np, 2np+1)
            int n  = np * 16 + b_row;
            int ch = c0 + b_cadd;
            u32 off = (u32)(n * 128 + (((ch ^ (n & 7)) & 7) << 4));
            u32 bh0, bh1, bh2, bh3, bl0, bl1, bl2, bl3;
            ldmx4(bh0, bh1, bh2, bh3, sb + SM_BHI + off);
            ldmx4(bl0, bl1, bl2, bl3, sb + SM_BLO + off);

            #pragma unroll
            for (int mt = 0; mt < 2; mt++) {
                mma_bf16(d[mt][2 * np],     ah[mt], bh0, bh1);   // hi*hi
                mma_bf16(d[mt][2 * np + 1], ah[mt], bh2, bh3);
                mma_bf16(d[mt][2 * np],     ah[mt], bl0, bl1);   // hi*lo
                mma_bf16(d[mt][2 * np + 1], ah[mt], bl2, bl3);
                mma_bf16(d[mt][2 * np],     al[mt], bh0, bh1);   // lo*hi
                mma_bf16(d[mt][2 * np + 1], al[mt], bh2, bh3);
            }
        }

        #pragma unroll
        for (int mt = 0; mt < 2; mt++)
            #pragma unroll
            for (int r = 0; r < 4; r++)
                xf[mt][r] = xn[mt][r];
    }

    // ---- epilogue: +bias, direct stores (each STG.64 group = full 32B sectors) ----
    const float* sBias = (const float*)(smem + SM_BIAS);
    #pragma unroll
    for (int mt = 0; mt < 2; mt++) {
        int r0 = rowBase + wid * 32 + mt * 16 + g;
        float* o0 = out + (size_t)r0 * (TT * OO) + (size_t)t * OO;
        float* o1 = o0 + (size_t)8 * (TT * OO);
        #pragma unroll
        for (int nt = 0; nt < 8; nt++) {
            int c = nt * 8 + 2 * q;
            float2 bv = *(const float2*)(sBias + c);
            float2 v0 = { d[mt][nt][0] + bv.x, d[mt][nt][1] + bv.y };
            float2 v1 = { d[mt][nt][2] + bv.x, d[mt][nt][3] + bv.y };
            *(float2*)(o0 + c) = v0;   // row r0
            *(float2*)(o1 + c) = v1;   // row r0 + 8
        }
    }
}

extern "C" void kernel_launch(void* const* d_in, const int* in_sizes, int n_in,
                              void* d_out, int out_size)
{
    const float* x    = (const float*)d_in[0];   // 512*1024*64 fp32
    const float* W    = (const float*)d_in[1];   // 1024*64*64 fp32
    const float* bias = (const float*)d_in[2];   // 1024*64 fp32
    float* out        = (float*)d_out;           // 512*1024*64 fp32

    cudaFuncSetAttribute(ParallelLinear_59133109732019_kernel,
                         cudaFuncAttributeMaxDynamicSharedMemorySize, SM_TOTAL);

    dim3 grid(BB / ROWS, TT);   // (4, 1024)
    ParallelLinear_59133109732019_kernel<<<grid, BLOCK, SM_TOTAL>>>(x, W, bias, out);
}

// round 7
// speedup vs baseline: 3.0571x; 1.2208x over previous
#include <cuda_runtime.h>
#include <cuda_bf16.h>
#include <cstdint>

// ParallelLinear: out[b,t,o] = sum_i x[b,t,i] * W[t,o,i] + bias[t,o]
// B=512, T=1024, ISIZE=OSIZE=64, fp32.
// R7: mma.sync bf16-split fp32 (D = Ahi*Bhi + Ahi*Blo + Alo*Bhi).
//   k-permuted fragments -> x loaded as LDG.128 (float4 = one A fragment half),
//   n-permuted B -> epilogue STG.128. Permutations baked into W smem staging.

#define TT    1024
#define BB    512
#define KK    64
#define OO    64
#define BLOCK 128
#define ROWS  128

typedef unsigned int u32;

// ---- smem byte offsets ----
#define SM_BIAS 0                          // 64 floats = 256 B
#define SM_BHI  256                        // 64 rows * 128 B = 8192
#define SM_BLO  (SM_BHI + OO * 128)
#define SM_TOTAL (SM_BLO + OO * 128)       // 16640

__device__ __forceinline__ u32 smem_u32(const void* p) {
    u32 a;
    asm("{ .reg .u64 t; cvta.to.shared.u64 t, %1; cvt.u32.u64 %0, t; }" : "=r"(a) : "l"(p));
    return a;
}

// split fp32 pair -> packed bf16x2 hi and lo
__device__ __forceinline__ void split2(float ax, float ay, u32 &hi, u32 &lo) {
    float2 v = { ax, ay };
    __nv_bfloat162 hp = __float22bfloat162_rn(v);
    u32 h = *(u32*)&hp;
    float hx = __uint_as_float(h << 16);
    float hy = __uint_as_float(h & 0xFFFF0000u);
    float2 r = { v.x - hx, v.y - hy };
    __nv_bfloat162 lp = __float22bfloat162_rn(r);
    hi = h;
    lo = *(u32*)&lp;
}

// W staging-write offset with XOR swizzle (row = staged n-position, ip = staged pair idx)
__device__ __forceinline__ u32 stage_off(int row, int ip) {
    return (u32)(row * 128 + ((((ip >> 2) ^ (row & 7)) & 7) << 4) + ((ip & 3) << 2));
}

__device__ __forceinline__ void ldmx4(u32 &r0, u32 &r1, u32 &r2, u32 &r3, u32 addr) {
    asm volatile("ldmatrix.sync.aligned.m8n8.x4.shared.b16 {%0,%1,%2,%3}, [%4];"
                 : "=r"(r0), "=r"(r1), "=r"(r2), "=r"(r3) : "r"(addr));
}

__device__ __forceinline__ void mma_bf16(float* d, const u32* a, u32 b0, u32 b1) {
    asm volatile(
        "mma.sync.aligned.m16n8k16.row.col.f32.bf16.bf16.f32 "
        "{%0,%1,%2,%3}, {%4,%5,%6,%7}, {%8,%9}, {%0,%1,%2,%3};"
        : "+f"(d[0]), "+f"(d[1]), "+f"(d[2]), "+f"(d[3])
        : "r"(a[0]), "r"(a[1]), "r"(a[2]), "r"(a[3]), "r"(b0), "r"(b1));
}

__global__ __launch_bounds__(BLOCK, 4)
void ParallelLinear_59133109732019_kernel(
    const float* __restrict__ x,     // [B, T, 64]
    const float* __restrict__ W,     // [T, 64, 64]  (W[t][o][i])
    const float* __restrict__ bias,  // [T, 64]
    float* __restrict__ out)         // [B, T, 64]
{
    extern __shared__ char smem[];
    const u32 sb = smem_u32(smem);

    const int t       = blockIdx.y;
    const int rowBase = blockIdx.x * ROWS;
    const int tid     = threadIdx.x;
    const int wid     = tid >> 5;
    const int lane    = tid & 31;
    const int g       = lane >> 2;       // row within 8-group
    const int q       = lane & 3;        // fragment column selector

    // x fragment base: rows (rowBase + wid*32 + mt*16 + g [+8]), col 4q (k-permuted)
    const size_t xrstride = (size_t)TT * KK;
    const float* xbase[2];
    #pragma unroll
    for (int mt = 0; mt < 2; mt++)
        xbase[mt] = x + (size_t)(rowBase + wid * 32 + mt * 16 + g) * xrstride
                      + (size_t)t * KK + 4 * q;

    // ---- prefetch ks=0 x data (one float4 = one A-fragment half) ----
    float4 xf[2][2];
    #pragma unroll
    for (int mt = 0; mt < 2; mt++) {
        xf[mt][0] = *(const float4*)(xbase[mt]);                  // row g
        xf[mt][1] = *(const float4*)(xbase[mt] + 8 * xrstride);   // row g+8
    }

    // ---- stage W[t] hi/lo with k-perm (sigma) and n-perm (pi) baked in ----
    {
        const float2* Wg = (const float2*)(W + (size_t)t * (OO * KK));
        #pragma unroll
        for (int k = 0; k < (OO * KK / 2) / BLOCK; k++) {  // 16 iters
            int p = k * BLOCK + tid;
            int o = p >> 5, ip = p & 31;                   // o row, source i-pair
            u32 hi, lo;
            float2 v = Wg[p];
            split2(v.x, v.y, hi, lo);
            // k-perm: pair cp within 16-block -> cp' = (cp&1)*4 + (cp>>1)
            int blk = ip >> 3, cp = ip & 7;
            int ipp = (blk << 3) | (((cp & 1) << 2) | (cp >> 1));
            // n-perm: o = 16m + 4q + 2b + j -> row' = 16m + 8b + 2q + j
            int m = o >> 4, qq = (o >> 2) & 3, bb = (o >> 1) & 1, j = o & 1;
            int rowp = (m << 4) | (bb << 3) | (qq << 1) | j;
            u32 off = stage_off(rowp, ipp);
            *(u32*)(smem + SM_BHI + off) = hi;
            *(u32*)(smem + SM_BLO + off) = lo;
        }
        if (tid < OO) ((float*)(smem + SM_BIAS))[tid] = bias[(size_t)t * OO + tid];
    }
    __syncthreads();

    // ---- accumulators: 2 m-tiles x 8 n-tiles x 4 fp32 ----
    float d[2][8][4];
    #pragma unroll
    for (int mt = 0; mt < 2; mt++)
        #pragma unroll
        for (int nt = 0; nt < 8; nt++)
            #pragma unroll
            for (int e = 0; e < 4; e++) d[mt][nt][e] = 0.0f;

    // B-fragment ldmatrix lane->address components
    const int b_row  = (lane & 7) + ((lane >> 4) << 3);
    const int b_cadd = (lane >> 3) & 1;

    #pragma unroll
    for (int ks = 0; ks < 4; ks++) {
        // prefetch next k-step's x
        float4 xn[2][2];
        if (ks < 3) {
            #pragma unroll
            for (int mt = 0; mt < 2; mt++) {
                const float* bp = xbase[mt] + (ks + 1) * 16;
                xn[mt][0] = *(const float4*)(bp);
                xn[mt][1] = *(const float4*)(bp + 8 * xrstride);
            }
        }

        // build bf16 hi/lo A fragments (k-permuted: float4 -> R0/R2, R1/R3)
        u32 ah[2][4], al[2][4];
        #pragma unroll
        for (int mt = 0; mt < 2; mt++) {
            split2(xf[mt][0].x, xf[mt][0].y, ah[mt][0], al[mt][0]);   // row g,   k-low
            split2(xf[mt][1].x, xf[mt][1].y, ah[mt][1], al[mt][1]);   // row g+8, k-low
            split2(xf[mt][0].z, xf[mt][0].w, ah[mt][2], al[mt][2]);   // row g,   k-high
            split2(xf[mt][1].z, xf[mt][1].w, ah[mt][3], al[mt][3]);   // row g+8, k-high
        }

        const int c0 = ks * 2;
        #pragma unroll
        for (int np = 0; np < 4; np++) {
            int n  = np * 16 + b_row;
            int ch = c0 + b_cadd;
            u32 off = (u32)(n * 128 + (((ch ^ (n & 7)) & 7) << 4));
            u32 bh0, bh1, bh2, bh3, bl0, bl1, bl2, bl3;
            ldmx4(bh0, bh1, bh2, bh3, sb + SM_BHI + off);
            ldmx4(bl0, bl1, bl2, bl3, sb + SM_BLO + off);

            #pragma unroll
            for (int mt = 0; mt < 2; mt++) {
                mma_bf16(d[mt][2 * np],     ah[mt], bh0, bh1);   // hi*hi
                mma_bf16(d[mt][2 * np + 1], ah[mt], bh2, bh3);
                mma_bf16(d[mt][2 * np],     ah[mt], bl0, bl1);   // hi*lo
                mma_bf16(d[mt][2 * np + 1], ah[mt], bl2, bl3);
                mma_bf16(d[mt][2 * np],     al[mt], bh0, bh1);   // lo*hi
                mma_bf16(d[mt][2 * np + 1], al[mt], bh2, bh3);
            }
        }

        #pragma unroll
        for (int mt = 0; mt < 2; mt++) {
            xf[mt][0] = xn[mt][0];
            xf[mt][1] = xn[mt][1];
        }
    }

    // ---- epilogue: n-perm makes nt-pairs contiguous -> STG.128 ----
    const float* sBias = (const float*)(smem + SM_BIAS);
    #pragma unroll
    for (int mt = 0; mt < 2; mt++) {
        int r0 = rowBase + wid * 32 + mt * 16 + g;
        float* o0 = out + (size_t)r0 * (TT * OO) + (size_t)t * OO;
        float* o1 = o0 + (size_t)8 * (TT * OO);
        #pragma unroll
        for (int m = 0; m < 4; m++) {
            int c = 16 * m + 4 * q;        // true cols c..c+3
            float4 bv = *(const float4*)(sBias + c);
            float4 v0 = { d[mt][2 * m][0] + bv.x, d[mt][2 * m][1] + bv.y,
                          d[mt][2 * m + 1][0] + bv.z, d[mt][2 * m + 1][1] + bv.w };
            float4 v1 = { d[mt][2 * m][2] + bv.x, d[mt][2 * m][3] + bv.y,
                          d[mt][2 * m + 1][2] + bv.z, d[mt][2 * m + 1][3] + bv.w };
            *(float4*)(o0 + c) = v0;       // row r0
            *(float4*)(o1 + c) = v1;       // row r0 + 8
        }
    }
}

extern "C" void kernel_launch(void* const* d_in, const int* in_sizes, int n_in,
                              void* d_out, int out_size)
{
    const float* x    = (const float*)d_in[0];   // 512*1024*64 fp32
    const float* W    = (const float*)d_in[1];   // 1024*64*64 fp32
    const float* bias = (const float*)d_in[2];   // 1024*64 fp32
    float* out        = (float*)d_out;           // 512*1024*64 fp32

    cudaFuncSetAttribute(ParallelLinear_59133109732019_kernel,
                         cudaFuncAttributeMaxDynamicSharedMemorySize, SM_TOTAL);

    dim3 grid(BB / ROWS, TT);   // (4, 1024)
    ParallelLinear_59133109732019_kernel<<<grid, BLOCK, SM_TOTAL>>>(x, W, bias, out);
}